// round 14
// baseline (speedup 1.0000x reference)
#include <cuda_runtime.h>
#include <cuda_fp16.h>
#include <cstdint>
#include <math.h>

#define Tt 512
#define Bb 64
#define Hh 1024
#define G4 4096
#define K2 2048
#define NBLK 64   // persistent blocks (16 units each)

// ---------------------------------------------------------------------------
// Device globals. Weight rows UNIT-MAJOR: j = u*4 + g, g in {i,f,c,o}.
// Chunk-major fp16 layouts; staging is pure cp.async.bulk byte copies.
// ---------------------------------------------------------------------------
__device__ __align__(128) __half g_xc[(size_t)256 * 32 * 5120];
__device__ __align__(128) __half g_wc[(size_t)32 * 32 * 5120];
__device__ __align__(128) __half g_Wh[(size_t)G4 * Hh];
__device__ float g_bias[G4];
// gx: [t=512][blk=64][64 rows * 68 cols] f32 (17408 B per (t,blk))
__device__ __align__(128) float g_gx2[(size_t)Tt * NBLK * 4352];
// h: [parity][ch=16][64 rows * 72 stride] fp16 (9216 B per chunk)
__device__ __align__(128) __half g_hbulk[2][16][4608];
// per-chunk producer arrival counters (4 producers each; padded lines)
__device__ volatile int g_ctr16[16 * 32];

// ---------------------------------------------------------------------------
// PTX helpers — non-'a' instructions only
// ---------------------------------------------------------------------------
__device__ __forceinline__ uint32_t smem_u32(const void* p) {
    uint32_t a;
    asm("{ .reg .u64 t; cvta.to.shared.u64 t, %1; cvt.u32.u64 %0, t; }" : "=r"(a) : "l"(p));
    return a;
}
__device__ __forceinline__ void cp16(uint32_t dst, const void* src) {
    asm volatile("cp.async.cg.shared.global [%0], [%1], 16;" :: "r"(dst), "l"(src) : "memory");
}
#define CP_COMMIT() asm volatile("cp.async.commit_group;" ::: "memory")
template <int N>
__device__ __forceinline__ void cp_wait() {
    asm volatile("cp.async.wait_group %0;" :: "n"(N) : "memory");
}
__device__ __forceinline__ void cp_bulk(uint32_t dst, const void* src, uint32_t bytes, uint32_t mbar) {
    asm volatile("cp.async.bulk.shared::cluster.global.mbarrier::complete_tx::bytes [%0], [%1], %2, [%3];"
                 :: "r"(dst), "l"(src), "r"(bytes), "r"(mbar) : "memory");
}
#define MBAR_INIT(mb, c)  asm volatile("mbarrier.init.shared.b64 [%0], %1;" :: "r"((uint32_t)(mb)), "r"((uint32_t)(c)) : "memory")
#define MBAR_EXPECT(mb, b) asm volatile("mbarrier.arrive.expect_tx.shared.b64 _, [%0], %1;" :: "r"((uint32_t)(mb)), "r"((uint32_t)(b)) : "memory")
#define MBAR_ARRIVE(mb)   asm volatile("mbarrier.arrive.shared.b64 _, [%0];" :: "r"((uint32_t)(mb)) : "memory")
#define MBAR_WAIT(mb, ph) do { \
    uint32_t _m = (uint32_t)(mb), _p = (uint32_t)(ph), _d; \
    asm volatile("{\n\t.reg .pred p;\n\tmbarrier.try_wait.parity.acquire.cta.shared::cta.b64 p, [%1], %2;\n\tselp.b32 %0, 1, 0, p;\n\t}" \
        : "=r"(_d) : "r"(_m), "r"(_p) : "memory"); \
    if (!_d) { \
        asm volatile("{\n\t.reg .pred P1;\n\tWL_%=: mbarrier.try_wait.parity.acquire.cta.shared::cta.b64 P1, [%0], %1, 0x989680;\n\t@P1 bra.uni WD_%=;\n\tbra.uni WL_%=;\n\tWD_%=:\n\t}" \
            :: "r"(_m), "r"(_p) : "memory"); \
    } \
} while (0)

__device__ __forceinline__ void mma_f16(float* c, const uint32_t* a, const uint32_t* b) {
    asm volatile(
        "mma.sync.aligned.m16n8k16.row.col.f32.f16.f16.f32 "
        "{%0,%1,%2,%3}, {%4,%5,%6,%7}, {%8,%9}, {%0,%1,%2,%3};"
        : "+f"(c[0]), "+f"(c[1]), "+f"(c[2]), "+f"(c[3])
        : "r"(a[0]), "r"(a[1]), "r"(a[2]), "r"(a[3]), "r"(b[0]), "r"(b[1]));
}
__device__ __forceinline__ void mma_f16b(float* c, const uint32_t* a, uint32_t b0, uint32_t b1) {
    asm volatile(
        "mma.sync.aligned.m16n8k16.row.col.f32.f16.f16.f32 "
        "{%0,%1,%2,%3}, {%4,%5,%6,%7}, {%8,%9}, {%0,%1,%2,%3};"
        : "+f"(c[0]), "+f"(c[1]), "+f"(c[2]), "+f"(c[3])
        : "r"(a[0]), "r"(a[1]), "r"(a[2]), "r"(a[3]), "r"(b0), "r"(b1));
}
__device__ __forceinline__ void ldsm_x4(uint32_t* r, uint32_t addr) {
    asm volatile("ldmatrix.sync.aligned.m8n8.x4.shared.b16 {%0,%1,%2,%3}, [%4];"
                 : "=r"(r[0]), "=r"(r[1]), "=r"(r[2]), "=r"(r[3]) : "r"(addr));
}
__device__ __forceinline__ void ldsm_x2(uint32_t* r, uint32_t addr) {
    asm volatile("ldmatrix.sync.aligned.m8n8.x2.shared.b16 {%0,%1}, [%2];"
                 : "=r"(r[0]), "=r"(r[1]) : "r"(addr));
}
__device__ __forceinline__ void nsleep() { asm volatile("nanosleep.u32 40;"); }
#define BAR_COMPUTE() asm volatile("bar.sync 1, 256;" ::: "memory")

__device__ __forceinline__ float sigf(float v) { return 1.0f / (1.0f + __expf(-v)); }
__device__ __forceinline__ float tanhf_fast(float v) {
    float e = __expf(-2.0f * fabsf(v));
    float r = (1.0f - e) / (1.0f + e);
    return (v >= 0.0f) ? r : -r;
}

// ---------------------------------------------------------------------------
// Prep kernels
// ---------------------------------------------------------------------------
__global__ void split_x_kernel(const float* __restrict__ x) {
    size_t total = (size_t)Tt * Bb * Hh;
    size_t stride = (size_t)gridDim.x * blockDim.x;
    for (size_t i = (size_t)blockIdx.x * blockDim.x + threadIdx.x; i < total; i += stride) {
        float v = x[i];
        size_t m = i >> 10;
        int k = (int)(i & 1023);
        size_t dst = ((m >> 7) * 32 + (k >> 5)) * 5120 + (m & 127) * 40 + (k & 31);
        g_xc[dst] = __float2half(v);
    }
}

__global__ void repack_kernel(const float* __restrict__ Wi, const float* __restrict__ Wf,
                              const float* __restrict__ Wc, const float* __restrict__ Wo,
                              const float* __restrict__ bi, const float* __restrict__ bf,
                              const float* __restrict__ bc, const float* __restrict__ bo) {
    size_t total = (size_t)G4 * K2;
    size_t stride = (size_t)gridDim.x * blockDim.x;
    for (size_t idx = (size_t)blockIdx.x * blockDim.x + threadIdx.x; idx < total; idx += stride) {
        int j = (int)(idx / K2);
        int k = (int)(idx % K2);
        int u = j >> 2, g = j & 3;
        const float* src = (g == 0) ? Wi : (g == 1) ? Wf : (g == 2) ? Wc : Wo;
        float v = src[(size_t)u * K2 + k];
        if (k < Hh) {
            size_t dst = ((size_t)(j >> 7) * 32 + (k >> 5)) * 5120 + (j & 127) * 40 + (k & 31);
            g_wc[dst] = __float2half(v);
        } else {
            g_Wh[(size_t)j * Hh + (k - Hh)] = __float2half(v);
        }
    }
    for (int j = blockIdx.x * blockDim.x + threadIdx.x; j < G4; j += (int)stride) {
        int u = j >> 2, g = j & 3;
        const float* sb = (g == 0) ? bi : (g == 1) ? bf : (g == 2) ? bc : bo;
        g_bias[j] = sb[u];
    }
}

__global__ void init_state_kernel() {
    int i = blockIdx.x * blockDim.x + threadIdx.x;
    int stride = gridDim.x * blockDim.x;
    __half z = __float2half(0.0f);
    for (int k = i; k < 16 * 4608; k += stride) {
        g_hbulk[0][k / 4608][k % 4608] = z;
    }
    for (int k = i; k < 16 * 32; k += stride) g_ctr16[k] = 0;
}

// ---------------------------------------------------------------------------
// x-GEMM: gx = x @ Wx^T + b, fp16 single-product via mma.sync.
// CTA 128x128, 8 warps, warp tile 64x32. K chunks of 32, 4-slot bulk ring
// with full/empty mbarrier pipeline. 2 CTAs/SM. (mainloop unchanged from R13)
// ---------------------------------------------------------------------------
#define RS 40
#define ARR (128 * RS * 2)              // 10240 B
#define SLOT (2 * ARR)                  // A + B
#define GX_MB (4 * SLOT)                // full[4] @ GX_MB, empty[4] @ GX_MB+32
#define GX_SMEM (GX_MB + 64)

__global__ __launch_bounds__(256, 2) void gemm_x_mma() {
    extern __shared__ char smem[];
    const uint32_t sbase = smem_u32(smem);
    const int tid = threadIdx.x;
    const int w = tid >> 5;
    const int lane = tid & 31;
    const int g = lane >> 2;
    const int t = lane & 3;
    const int nblk = blockIdx.x;
    const int mblk = blockIdx.y;
    const int n0 = nblk * 128;
    const int m0 = mblk * 128;
    const int wm = (w >> 2) * 64;
    const int wn = (w & 3) * 32;
    const int lrow = (lane & 7) + ((lane >> 3) & 1) * 8;
    const int lcol = (lane >> 4) * 8;

    if (tid == 0) {
#pragma unroll
        for (int s = 0; s < 4; s++) {
            MBAR_INIT(sbase + GX_MB + s * 8, 1);        // full (tx-based)
            MBAR_INIT(sbase + GX_MB + 32 + s * 8, 8);   // empty (8 warp arrivals)
        }
    }
    __syncthreads();

    auto stage = [&](int c) {
        uint32_t base = sbase + (uint32_t)(c & 3) * SLOT;
        uint32_t mb = sbase + GX_MB + (c & 3) * 8;
        MBAR_EXPECT(mb, SLOT);
        cp_bulk(base, g_xc + ((size_t)mblk * 32 + c) * 5120, ARR, mb);
        cp_bulk(base + ARR, g_wc + ((size_t)nblk * 32 + c) * 5120, ARR, mb);
    };

    float C[4][4][4];
#pragma unroll
    for (int i = 0; i < 4; i++)
#pragma unroll
        for (int j = 0; j < 4; j++)
#pragma unroll
            for (int q = 0; q < 4; q++) C[i][j][q] = 0.0f;

    const uint32_t a_off = (uint32_t)((wm + lrow) * RS + lcol) * 2;
    const uint32_t b_off = (uint32_t)((wn + lrow) * RS + lcol) * 2;

    if (tid == 0) { stage(0); stage(1); stage(2); }
    for (int ch = 0; ch < 32; ch++) {
        if (tid == 0 && ch < 29) {
            int c = ch + 3;
            if (c >= 4) MBAR_WAIT(sbase + GX_MB + 32 + (c & 3) * 8, ((c >> 2) - 1) & 1);
            stage(c);
        }
        MBAR_WAIT(sbase + GX_MB + (ch & 3) * 8, (ch >> 2) & 1);
        const uint32_t buf = sbase + (uint32_t)(ch & 3) * SLOT;
#pragma unroll
        for (int kk = 0; kk < 32; kk += 16) {
            uint32_t ah[4][4], bh[2][4];
#pragma unroll
            for (int mt = 0; mt < 4; mt++)
                ldsm_x4(ah[mt], buf + a_off + (uint32_t)(mt * 16 * RS + kk) * 2);
#pragma unroll
            for (int p = 0; p < 2; p++)
                ldsm_x4(bh[p], buf + ARR + b_off + (uint32_t)(p * 16 * RS + kk) * 2);
#pragma unroll
            for (int mt = 0; mt < 4; mt++)
#pragma unroll
                for (int nt = 0; nt < 4; nt++) {
                    int p = nt >> 1, s = nt & 1;
                    mma_f16b(C[mt][nt], ah[mt], bh[p][s], bh[p][s + 2]);
                }
        }
        if (lane == 0) MBAR_ARRIVE(sbase + GX_MB + 32 + (ch & 3) * 8);
    }

    // Epilogue: add bias, store into chunk-major gx2 (64-block layout)
#pragma unroll
    for (int mt = 0; mt < 4; mt++) {
        int row = m0 + wm + mt * 16 + g;
        int t_idx = row >> 6;
        int batch = row & 63;
#pragma unroll
        for (int nt = 0; nt < 4; nt++) {
            int col = n0 + wn + nt * 8 + 2 * t;
            int buI = col >> 6;
            int cs = col & 63;
            float2 bv = *reinterpret_cast<const float2*>(g_bias + col);
            float2 o0 = { C[mt][nt][0] + bv.x, C[mt][nt][1] + bv.y };
            float2 o1 = { C[mt][nt][2] + bv.x, C[mt][nt][3] + bv.y };
            float* dst = g_gx2 + ((size_t)t_idx * NBLK + buI) * 4352;
            *reinterpret_cast<float2*>(dst + batch * 68 + cs) = o0;
            *reinterpret_cast<float2*>(dst + (batch + 8) * 68 + cs) = o1;
        }
    }
}

// ---------------------------------------------------------------------------
// Persistent recurrent kernel: 64 blocks x 288 threads (8 compute warps +
// 1 staging warp). Each block owns 16 units (64 gate rows). h broadcast is
// halved vs 128 blocks. 8 smem h-slots in 2 slot-groups, 4 chunk groups per
// step; per-group full (count 4) + empty (count 8) mbarriers, one completion
// each per step (parity t&1 / (t-1)&1).
// SMEM (bytes):
//   WH [64][1032] fp16 @ 0          (132096)
//   H slots: 8 x 9216 @ 132096     (73728)
//   GXS [64][68] f32 @ 205824      (17408)
//   mbarriers @ 223232: full[4], empty[4] @ +32, gx @ +64 -> total 223304
// ---------------------------------------------------------------------------
#define WH_OFF 0
#define HB_OFF 132096
#define HCH_SZ 9216
#define GXS_OFF 205824
#define PMB_OFF 223232
#define PERSIST_SMEM 223304

__global__ __launch_bounds__(288, 1) void lstm_persist(float* __restrict__ out) {
    extern __shared__ char smem[];
    const uint32_t sbase = smem_u32(smem);
    const int tid = threadIdx.x;
    const int bu = blockIdx.x;          // 0..63
    const int chunk0 = bu >> 2;         // own chunk (this block is 1 of its 4 producers)

    if (tid == 0) {
#pragma unroll
        for (int s = 0; s < 4; s++) {
            MBAR_INIT(sbase + PMB_OFF + s * 8, 4);       // full_k: 4 staging lanes
            MBAR_INIT(sbase + PMB_OFF + 32 + s * 8, 8);  // empty_k: 8 compute warps
        }
        MBAR_INIT(sbase + PMB_OFF + 64, 1);              // gx
    }
    __syncthreads();   // only block-wide sync; before divergence

    // ======================= staging warp =======================
    if (tid >= 256) {
        int L = tid - 256;              // consume position 0..15
        if (L < 16) {
            const int k = L >> 2;                       // chunk group 0..3
            const int ch = (chunk0 + L) & 15;
            const int slot = L & 7;                     // slot-group (k&1)
            const uint32_t fullmb = sbase + PMB_OFF + k * 8;
            // slot reuse gate: group k reuses slots of group (k+2)&3
            const uint32_t emptymb = sbase + PMB_OFF + 32 + ((k + 2) & 3) * 8;
            const uint32_t dst = sbase + HB_OFF + (uint32_t)slot * HCH_SZ;
            for (int t = 0; t < Tt; t++) {
                if (k >= 2) {
                    MBAR_WAIT(emptymb, t & 1);          // g0/g1 of this step consumed
                } else if (t > 0) {
                    MBAR_WAIT(emptymb, (t - 1) & 1);    // g2/g3 of prev step consumed
                }
                if (t > 0) {
                    while (g_ctr16[ch * 32] < 4 * t) nsleep();   // producers arrived
                    __threadfence();
                }
                MBAR_EXPECT(fullmb, HCH_SZ);
                cp_bulk(dst, (const char*)&g_hbulk[t & 1][0][0] + (size_t)ch * HCH_SZ,
                        HCH_SZ, fullmb);
            }
        }
        return;
    }

    // ======================= compute warps =======================
    const int w = tid >> 5;             // 0..7, owns gate cols [8w, 8w+8)
    const int lane = tid & 31;
    const int g = lane >> 2;
    const int tq = lane & 3;

    // ---- load Wh slice into smem (once): rows bu*64 .. +64 ----
    {
        const __half* ws = g_Wh + (size_t)bu * 64 * Hh;
#pragma unroll
        for (int q = 0; q < 32; q++) {
            int idx = q * 256 + tid;            // 0..8191
            int row = idx >> 7;                 // 0..63
            int seg = idx & 127;
            cp16(sbase + WH_OFF + (uint32_t)(row * 1032 + seg * 8) * 2,
                 ws + (size_t)row * Hh + seg * 8);
        }
        CP_COMMIT();
        cp_wait<0>();
    }
    BAR_COMPUTE();

    const int lrow = (lane & 7) + ((lane >> 3) & 1) * 8;
    const int lcol = (lane >> 4) * 8;
    const uint32_t a_lane_off = (uint32_t)(lrow * 72 + lcol) * 2;
    const uint32_t b_lane_off = (uint32_t)((w * 8 + (lane & 7)) * 1032 + ((lane >> 3) & 1) * 8) * 2;
    const uint32_t b_base = sbase + WH_OFF + b_lane_off;

    const int u_glob = bu * 16 + 2 * w + (tq >> 1);
    const int u_ch = u_glob >> 6;       // == bu >> 2
    const int u_c = u_glob & 63;
    const int gcol = 8 * w + 2 * tq;

    float creg[4][2];
    float hlast[4][2];
#pragma unroll
    for (int mt = 0; mt < 4; mt++) { creg[mt][0] = 0.0f; creg[mt][1] = 0.0f; }

    const float* gxs = reinterpret_cast<const float*>(smem + GXS_OFF);
    const uint32_t mb_gx = sbase + PMB_OFF + 64;

    for (int t = 0; t < Tt; t++) {
        if (tid == 1) {
            MBAR_EXPECT(mb_gx, 17408);
            cp_bulk(sbase + GXS_OFF, g_gx2 + ((size_t)t * NBLK + bu) * 4352, 17408, mb_gx);
        }

        float C[4][4];
#pragma unroll
        for (int mt = 0; mt < 4; mt++)
#pragma unroll
            for (int q = 0; q < 4; q++) C[mt][q] = 0.0f;

        for (int i = 0; i < 16; i++) {
            if ((i & 3) == 0) MBAR_WAIT(sbase + PMB_OFF + (i >> 2) * 8, t & 1);
            const int slot = i & 7;
            const int ch = (i + chunk0) & 15;

            const uint32_t abuf = sbase + HB_OFF + (uint32_t)slot * HCH_SZ + a_lane_off;
            const uint32_t bco = (uint32_t)ch * 128;  // 64 cols * 2B within WH

            uint32_t fa[2][4][4], fb[2][2];
            ldsm_x2(fb[0], b_base + bco);
#pragma unroll
            for (int mt = 0; mt < 4; mt++) ldsm_x4(fa[0][mt], abuf + mt * 2304);
#pragma unroll
            for (int k16 = 0; k16 < 4; k16++) {
                int cur = k16 & 1;
                if (k16 < 3) {
                    int nb = cur ^ 1;
                    uint32_t kb = (uint32_t)(k16 + 1) * 32;
                    ldsm_x2(fb[nb], b_base + bco + kb);
#pragma unroll
                    for (int mt = 0; mt < 4; mt++)
                        ldsm_x4(fa[nb][mt], abuf + mt * 2304 + kb);
                }
#pragma unroll
                for (int mt = 0; mt < 4; mt++)
                    mma_f16(C[mt], fa[cur][mt], fb[cur]);
            }
            if ((i & 3) == 3 && lane == 0)
                MBAR_ARRIVE(sbase + PMB_OFF + 32 + (i >> 2) * 8);  // empty_k
        }

        // ---- epilogue ----
        MBAR_WAIT(mb_gx, t & 1);
        float v[4][4], p[4][4];
#pragma unroll
        for (int mt = 0; mt < 4; mt++) {
            int r0 = mt * 16 + g;
            int r1 = r0 + 8;
            v[mt][0] = C[mt][0] + gxs[r0 * 68 + gcol];
            v[mt][1] = C[mt][1] + gxs[r0 * 68 + gcol + 1];
            v[mt][2] = C[mt][2] + gxs[r1 * 68 + gcol];
            v[mt][3] = C[mt][3] + gxs[r1 * 68 + gcol + 1];
        }
#pragma unroll
        for (int mt = 0; mt < 4; mt++)
#pragma unroll
            for (int q = 0; q < 4; q++)
                p[mt][q] = __shfl_xor_sync(0xffffffffu, v[mt][q], 1);

        const int np = (t + 1) & 1;
        __half* hb = &g_hbulk[np][u_ch][0];
#pragma unroll
        for (int mt = 0; mt < 4; mt++) {
            float ii0, ff0, cc0, oo0, ii1, ff1, cc1, oo1;
            if ((tq & 1) == 0) {
                ii0 = v[mt][0]; ff0 = v[mt][1]; cc0 = p[mt][0]; oo0 = p[mt][1];
                ii1 = v[mt][2]; ff1 = v[mt][3]; cc1 = p[mt][2]; oo1 = p[mt][3];
            } else {
                ii0 = p[mt][0]; ff0 = p[mt][1]; cc0 = v[mt][0]; oo0 = v[mt][1];
                ii1 = p[mt][2]; ff1 = p[mt][3]; cc1 = v[mt][2]; oo1 = v[mt][3];
            }
            float cn0 = fmaf(sigf(ff0), creg[mt][0], sigf(ii0) * tanhf_fast(cc0));
            float cn1 = fmaf(sigf(ff1), creg[mt][1], sigf(ii1) * tanhf_fast(cc1));
            creg[mt][0] = cn0; creg[mt][1] = cn1;
            float hn0 = sigf(oo0) * tanhf_fast(cn0);
            float hn1 = sigf(oo1) * tanhf_fast(cn1);
            hlast[mt][0] = hn0; hlast[mt][1] = hn1;
            int r0 = mt * 16 + g;
            hb[r0 * 72 + u_c] = __float2half(hn0);
            hb[(r0 + 8) * 72 + u_c] = __float2half(hn1);
        }

        // compute-warp barrier: all h stores done + all slot reads done
        BAR_COMPUTE();
        if (tid == 0) {
            __threadfence();
            atomicAdd((int*)&g_ctr16[u_ch * 32], 1);   // producer arrival
        }

        // hide out-seq stores behind next staging
#pragma unroll
        for (int mt = 0; mt < 4; mt++) {
            int r0 = mt * 16 + g;
            out[(size_t)t * (Bb * Hh) + r0 * Hh + u_glob] = hlast[mt][0];
            out[(size_t)t * (Bb * Hh) + (r0 + 8) * Hh + u_glob] = hlast[mt][1];
        }
    }

    // final h_T, c_T
    size_t base = (size_t)Tt * Bb * Hh;
#pragma unroll
    for (int mt = 0; mt < 4; mt++) {
        int r0 = mt * 16 + g;
        out[base + r0 * Hh + u_glob] = hlast[mt][0];
        out[base + (r0 + 8) * Hh + u_glob] = hlast[mt][1];
        out[base + Bb * Hh + r0 * Hh + u_glob] = creg[mt][0];
        out[base + Bb * Hh + (r0 + 8) * Hh + u_glob] = creg[mt][1];
    }
}

// ---------------------------------------------------------------------------
extern "C" void kernel_launch(void* const* d_in, const int* in_sizes, int n_in,
                              void* d_out, int out_size) {
    const float* x  = (const float*)d_in[0];
    const float* Wi = (const float*)d_in[1];
    const float* bi = (const float*)d_in[2];
    const float* Wf = (const float*)d_in[3];
    const float* bf = (const float*)d_in[4];
    const float* Wc = (const float*)d_in[5];
    const float* bc = (const float*)d_in[6];
    const float* Wo = (const float*)d_in[7];
    const float* bo = (const float*)d_in[8];
    float* out = (float*)d_out;

    cudaFuncSetAttribute(gemm_x_mma, cudaFuncAttributeMaxDynamicSharedMemorySize, GX_SMEM);
    cudaFuncSetAttribute(lstm_persist, cudaFuncAttributeMaxDynamicSharedMemorySize, PERSIST_SMEM);

    repack_kernel<<<512, 256>>>(Wi, Wf, Wc, Wo, bi, bf, bc, bo);
    split_x_kernel<<<1024, 256>>>(x);
    init_state_kernel<<<512, 256>>>();

    gemm_x_mma<<<dim3(G4 / 128, (Tt * Bb) / 128), 256, GX_SMEM>>>();

    lstm_persist<<<NBLK, 288, PERSIST_SMEM>>>(out);
}

// round 15
// speedup vs baseline: 1.6260x; 1.6260x over previous
#include <cuda_runtime.h>
#include <cuda_fp16.h>
#include <cstdint>
#include <math.h>

#define Tt 512
#define Bb 64
#define Hh 1024
#define G4 4096
#define K2 2048
#define NBLK 128

// ---------------------------------------------------------------------------
// Device globals. Weight rows UNIT-MAJOR: j = u*4 + g, g in {i,f,c,o}.
// Chunk-major fp16 layouts; staging is pure cp.async.bulk byte copies.
// ---------------------------------------------------------------------------
__device__ __align__(128) __half g_xc[(size_t)256 * 32 * 5120];
__device__ __align__(128) __half g_wc[(size_t)32 * 32 * 5120];
__device__ __align__(128) __half g_Wh[(size_t)G4 * Hh];
__device__ float g_bias[G4];
// gx: [t=512][blk=128][64 rows * 36 cols] f32 (9216 B per (t,blk))
__device__ __align__(128) float g_gx2[(size_t)Tt * NBLK * 2304];
// h: [parity][ch=16][64 rows * 72 stride] fp16 (9216 B per chunk)
__device__ __align__(128) __half g_hbulk[2][16][4608];
// per-chunk producer arrival counters (64 warp-arrivals per chunk per step)
__device__ volatile int g_ctr16[16 * 32];

// ---------------------------------------------------------------------------
// PTX helpers — non-'a' instructions only
// ---------------------------------------------------------------------------
__device__ __forceinline__ uint32_t smem_u32(const void* p) {
    uint32_t a;
    asm("{ .reg .u64 t; cvta.to.shared.u64 t, %1; cvt.u32.u64 %0, t; }" : "=r"(a) : "l"(p));
    return a;
}
__device__ __forceinline__ void cp16(uint32_t dst, const void* src) {
    asm volatile("cp.async.cg.shared.global [%0], [%1], 16;" :: "r"(dst), "l"(src) : "memory");
}
#define CP_COMMIT() asm volatile("cp.async.commit_group;" ::: "memory")
template <int N>
__device__ __forceinline__ void cp_wait() {
    asm volatile("cp.async.wait_group %0;" :: "n"(N) : "memory");
}
__device__ __forceinline__ void cp_bulk(uint32_t dst, const void* src, uint32_t bytes, uint32_t mbar) {
    asm volatile("cp.async.bulk.shared::cluster.global.mbarrier::complete_tx::bytes [%0], [%1], %2, [%3];"
                 :: "r"(dst), "l"(src), "r"(bytes), "r"(mbar) : "memory");
}
#define MBAR_INIT(mb, c)  asm volatile("mbarrier.init.shared.b64 [%0], %1;" :: "r"((uint32_t)(mb)), "r"((uint32_t)(c)) : "memory")
#define MBAR_EXPECT(mb, b) asm volatile("mbarrier.arrive.expect_tx.shared.b64 _, [%0], %1;" :: "r"((uint32_t)(mb)), "r"((uint32_t)(b)) : "memory")
#define MBAR_ARRIVE(mb)   asm volatile("mbarrier.arrive.shared.b64 _, [%0];" :: "r"((uint32_t)(mb)) : "memory")
#define MBAR_WAIT(mb, ph) do { \
    uint32_t _m = (uint32_t)(mb), _p = (uint32_t)(ph), _d; \
    asm volatile("{\n\t.reg .pred p;\n\tmbarrier.try_wait.parity.acquire.cta.shared::cta.b64 p, [%1], %2;\n\tselp.b32 %0, 1, 0, p;\n\t}" \
        : "=r"(_d) : "r"(_m), "r"(_p) : "memory"); \
    if (!_d) { \
        asm volatile("{\n\t.reg .pred P1;\n\tWL_%=: mbarrier.try_wait.parity.acquire.cta.shared::cta.b64 P1, [%0], %1, 0x989680;\n\t@P1 bra.uni WD_%=;\n\tbra.uni WL_%=;\n\tWD_%=:\n\t}" \
            :: "r"(_m), "r"(_p) : "memory"); \
    } \
} while (0)

__device__ __forceinline__ void red_release_gpu(int* p, int v) {
    asm volatile("red.release.gpu.global.add.s32 [%0], %1;" :: "l"(p), "r"(v) : "memory");
}

__device__ __forceinline__ void mma_f16(float* c, const uint32_t* a, const uint32_t* b) {
    asm volatile(
        "mma.sync.aligned.m16n8k16.row.col.f32.f16.f16.f32 "
        "{%0,%1,%2,%3}, {%4,%5,%6,%7}, {%8,%9}, {%0,%1,%2,%3};"
        : "+f"(c[0]), "+f"(c[1]), "+f"(c[2]), "+f"(c[3])
        : "r"(a[0]), "r"(a[1]), "r"(a[2]), "r"(a[3]), "r"(b[0]), "r"(b[1]));
}
__device__ __forceinline__ void mma_f16b(float* c, const uint32_t* a, uint32_t b0, uint32_t b1) {
    asm volatile(
        "mma.sync.aligned.m16n8k16.row.col.f32.f16.f16.f32 "
        "{%0,%1,%2,%3}, {%4,%5,%6,%7}, {%8,%9}, {%0,%1,%2,%3};"
        : "+f"(c[0]), "+f"(c[1]), "+f"(c[2]), "+f"(c[3])
        : "r"(a[0]), "r"(a[1]), "r"(a[2]), "r"(a[3]), "r"(b0), "r"(b1));
}
__device__ __forceinline__ void ldsm_x4(uint32_t* r, uint32_t addr) {
    asm volatile("ldmatrix.sync.aligned.m8n8.x4.shared.b16 {%0,%1,%2,%3}, [%4];"
                 : "=r"(r[0]), "=r"(r[1]), "=r"(r[2]), "=r"(r[3]) : "r"(addr));
}
__device__ __forceinline__ void ldsm_x2(uint32_t* r, uint32_t addr) {
    asm volatile("ldmatrix.sync.aligned.m8n8.x2.shared.b16 {%0,%1}, [%2];"
                 : "=r"(r[0]), "=r"(r[1]) : "r"(addr));
}
__device__ __forceinline__ void nsleep() { asm volatile("nanosleep.u32 40;"); }
#define BAR_COMPUTE() asm volatile("bar.sync 1, 256;" ::: "memory")

__device__ __forceinline__ float sigf(float v) { return 1.0f / (1.0f + __expf(-v)); }
__device__ __forceinline__ float tanhf_fast(float v) {
    float e = __expf(-2.0f * fabsf(v));
    float r = (1.0f - e) / (1.0f + e);
    return (v >= 0.0f) ? r : -r;
}

// ---------------------------------------------------------------------------
// Prep kernels
// ---------------------------------------------------------------------------
__global__ void split_x_kernel(const float* __restrict__ x) {
    size_t total = (size_t)Tt * Bb * Hh;
    size_t stride = (size_t)gridDim.x * blockDim.x;
    for (size_t i = (size_t)blockIdx.x * blockDim.x + threadIdx.x; i < total; i += stride) {
        float v = x[i];
        size_t m = i >> 10;
        int k = (int)(i & 1023);
        size_t dst = ((m >> 7) * 32 + (k >> 5)) * 5120 + (m & 127) * 40 + (k & 31);
        g_xc[dst] = __float2half(v);
    }
}

__global__ void repack_kernel(const float* __restrict__ Wi, const float* __restrict__ Wf,
                              const float* __restrict__ Wc, const float* __restrict__ Wo,
                              const float* __restrict__ bi, const float* __restrict__ bf,
                              const float* __restrict__ bc, const float* __restrict__ bo) {
    size_t total = (size_t)G4 * K2;
    size_t stride = (size_t)gridDim.x * blockDim.x;
    for (size_t idx = (size_t)blockIdx.x * blockDim.x + threadIdx.x; idx < total; idx += stride) {
        int j = (int)(idx / K2);
        int k = (int)(idx % K2);
        int u = j >> 2, g = j & 3;
        const float* src = (g == 0) ? Wi : (g == 1) ? Wf : (g == 2) ? Wc : Wo;
        float v = src[(size_t)u * K2 + k];
        if (k < Hh) {
            size_t dst = ((size_t)(j >> 7) * 32 + (k >> 5)) * 5120 + (j & 127) * 40 + (k & 31);
            g_wc[dst] = __float2half(v);
        } else {
            g_Wh[(size_t)j * Hh + (k - Hh)] = __float2half(v);
        }
    }
    for (int j = blockIdx.x * blockDim.x + threadIdx.x; j < G4; j += (int)stride) {
        int u = j >> 2, g = j & 3;
        const float* sb = (g == 0) ? bi : (g == 1) ? bf : (g == 2) ? bc : bo;
        g_bias[j] = sb[u];
    }
}

__global__ void init_state_kernel() {
    int i = blockIdx.x * blockDim.x + threadIdx.x;
    int stride = gridDim.x * blockDim.x;
    __half z = __float2half(0.0f);
    for (int k = i; k < 16 * 4608; k += stride) {
        g_hbulk[0][k / 4608][k % 4608] = z;
    }
    for (int k = i; k < 16 * 32; k += stride) g_ctr16[k] = 0;
}

// ---------------------------------------------------------------------------
// x-GEMM: gx = x @ Wx^T + b, fp16 single-product via mma.sync.
// CTA 128x128, 8 warps, warp tile 64x32. K chunks of 32, 4-slot bulk ring
// with full/empty mbarrier pipeline. 2 CTAs/SM. (unchanged from R13)
// ---------------------------------------------------------------------------
#define RS 40
#define ARR (128 * RS * 2)              // 10240 B
#define SLOT (2 * ARR)                  // A + B
#define GX_MB (4 * SLOT)                // full[4] @ GX_MB, empty[4] @ GX_MB+32
#define GX_SMEM (GX_MB + 64)

__global__ __launch_bounds__(256, 2) void gemm_x_mma() {
    extern __shared__ char smem[];
    const uint32_t sbase = smem_u32(smem);
    const int tid = threadIdx.x;
    const int w = tid >> 5;
    const int lane = tid & 31;
    const int g = lane >> 2;
    const int t = lane & 3;
    const int nblk = blockIdx.x;
    const int mblk = blockIdx.y;
    const int n0 = nblk * 128;
    const int m0 = mblk * 128;
    const int wm = (w >> 2) * 64;
    const int wn = (w & 3) * 32;
    const int lrow = (lane & 7) + ((lane >> 3) & 1) * 8;
    const int lcol = (lane >> 4) * 8;

    if (tid == 0) {
#pragma unroll
        for (int s = 0; s < 4; s++) {
            MBAR_INIT(sbase + GX_MB + s * 8, 1);        // full (tx-based)
            MBAR_INIT(sbase + GX_MB + 32 + s * 8, 8);   // empty (8 warp arrivals)
        }
    }
    __syncthreads();

    auto stage = [&](int c) {
        uint32_t base = sbase + (uint32_t)(c & 3) * SLOT;
        uint32_t mb = sbase + GX_MB + (c & 3) * 8;
        MBAR_EXPECT(mb, SLOT);
        cp_bulk(base, g_xc + ((size_t)mblk * 32 + c) * 5120, ARR, mb);
        cp_bulk(base + ARR, g_wc + ((size_t)nblk * 32 + c) * 5120, ARR, mb);
    };

    float C[4][4][4];
#pragma unroll
    for (int i = 0; i < 4; i++)
#pragma unroll
        for (int j = 0; j < 4; j++)
#pragma unroll
            for (int q = 0; q < 4; q++) C[i][j][q] = 0.0f;

    const uint32_t a_off = (uint32_t)((wm + lrow) * RS + lcol) * 2;
    const uint32_t b_off = (uint32_t)((wn + lrow) * RS + lcol) * 2;

    if (tid == 0) { stage(0); stage(1); stage(2); }
    for (int ch = 0; ch < 32; ch++) {
        if (tid == 0 && ch < 29) {
            int c = ch + 3;
            if (c >= 4) MBAR_WAIT(sbase + GX_MB + 32 + (c & 3) * 8, ((c >> 2) - 1) & 1);
            stage(c);
        }
        MBAR_WAIT(sbase + GX_MB + (ch & 3) * 8, (ch >> 2) & 1);
        const uint32_t buf = sbase + (uint32_t)(ch & 3) * SLOT;
#pragma unroll
        for (int kk = 0; kk < 32; kk += 16) {
            uint32_t ah[4][4], bh[2][4];
#pragma unroll
            for (int mt = 0; mt < 4; mt++)
                ldsm_x4(ah[mt], buf + a_off + (uint32_t)(mt * 16 * RS + kk) * 2);
#pragma unroll
            for (int p = 0; p < 2; p++)
                ldsm_x4(bh[p], buf + ARR + b_off + (uint32_t)(p * 16 * RS + kk) * 2);
#pragma unroll
            for (int mt = 0; mt < 4; mt++)
#pragma unroll
                for (int nt = 0; nt < 4; nt++) {
                    int p = nt >> 1, s = nt & 1;
                    mma_f16b(C[mt][nt], ah[mt], bh[p][s], bh[p][s + 2]);
                }
        }
        if (lane == 0) MBAR_ARRIVE(sbase + GX_MB + 32 + (ch & 3) * 8);
    }

    // Epilogue: add bias, store into chunk-major gx2
#pragma unroll
    for (int mt = 0; mt < 4; mt++) {
        int row = m0 + wm + mt * 16 + g;
        int t_idx = row >> 6;
        int batch = row & 63;
#pragma unroll
        for (int nt = 0; nt < 4; nt++) {
            int col = n0 + wn + nt * 8 + 2 * t;
            int buI = col >> 5;
            int cs = col & 31;
            float2 bv = *reinterpret_cast<const float2*>(g_bias + col);
            float2 o0 = { C[mt][nt][0] + bv.x, C[mt][nt][1] + bv.y };
            float2 o1 = { C[mt][nt][2] + bv.x, C[mt][nt][3] + bv.y };
            float* dst = g_gx2 + ((size_t)t_idx * NBLK + buI) * 2304;
            *reinterpret_cast<float2*>(dst + batch * 36 + cs) = o0;
            *reinterpret_cast<float2*>(dst + (batch + 8) * 36 + cs) = o1;
        }
    }
}

// ---------------------------------------------------------------------------
// Persistent recurrent kernel: 128 blocks x 288 threads (8 compute warps +
// 1 staging warp). R13 structure with:
//   - gx prefetched into registers per thread (no bulk, no epilogue wait)
//   - per-warp early producer arrivals (syncwarp + lane0 red.release)
// SMEM (bytes):
//   WH [32][1032] fp16 @ 0          (66048)
//   H slots: 16 x 9216 @ 66048      (147456)
//   mbarriers @ 213504 (4 group), step_done @ 213536 -> total 213544
// ---------------------------------------------------------------------------
#define WH_OFF 0
#define HB_OFF 66048
#define HCH_SZ 9216
#define PMB_OFF 213504
#define SDONE_OFF 213536
#define PERSIST_SMEM 213544

__global__ __launch_bounds__(288, 1) void lstm_persist(float* __restrict__ out) {
    extern __shared__ char smem[];
    const uint32_t sbase = smem_u32(smem);
    const int tid = threadIdx.x;
    const int bu = blockIdx.x;
    volatile int* sdone = (volatile int*)(smem + SDONE_OFF);
    const int chunk0 = bu >> 3;

    if (tid == 0) {
#pragma unroll
        for (int s = 0; s < 4; s++) MBAR_INIT(sbase + PMB_OFF + s * 8, 4);  // groups
        *sdone = 0;
    }
    __syncthreads();   // only block-wide sync; before divergence

    // ======================= staging warp =======================
    if (tid >= 256) {
        int L = tid - 256;          // consume position 0..15
        if (L < 16) {
            const int ch = (chunk0 + L) & 15;
            const uint32_t mb = sbase + PMB_OFF + (L >> 2) * 8;   // group barrier
            const uint32_t dst = sbase + HB_OFF + (uint32_t)ch * HCH_SZ;
            for (int t = 0; t < Tt; t++) {
                if (t > 0) {
                    while (*sdone < t) nsleep();                   // local slots free
                    while (g_ctr16[ch * 32] < 64 * t) nsleep();    // 64 warp arrivals
                    __threadfence();
                }
                MBAR_EXPECT(mb, HCH_SZ);
                cp_bulk(dst, (const char*)&g_hbulk[t & 1][0][0] + (size_t)ch * HCH_SZ,
                        HCH_SZ, mb);
            }
        }
        return;
    }

    // ======================= compute warps =======================
    const int w = tid >> 5;
    const int lane = tid & 31;
    const int g = lane >> 2;
    const int tq = lane & 3;
    const int wm = (w >> 2) * 32;   // 0 or 32
    const int wn = (w & 3) * 8;     // 0,8,16,24

    // ---- load Wh slice into smem (once) ----
    {
        const __half* ws = g_Wh + (size_t)bu * 32 * Hh;
#pragma unroll
        for (int q = 0; q < 16; q++) {
            int idx = q * 256 + tid;
            int row = idx >> 7;
            int seg = idx & 127;
            cp16(sbase + WH_OFF + (uint32_t)(row * 1032 + seg * 8) * 2,
                 ws + (size_t)row * Hh + seg * 8);
        }
        CP_COMMIT();
        cp_wait<0>();
    }
    BAR_COMPUTE();

    const int lrow = (lane & 7) + ((lane >> 3) & 1) * 8;
    const int lcol = (lane >> 4) * 8;
    const uint32_t a_lane_off = (uint32_t)((wm + lrow) * 72 + lcol) * 2;
    const uint32_t b_lane_off = (uint32_t)((wn + (lane & 7)) * 1032 + ((lane >> 3) & 1) * 8) * 2;
    const uint32_t b_base = sbase + WH_OFF + b_lane_off;

    const int myMt = tq & 1;
    const int row0 = wm + myMt * 16 + g;
    const int row1 = row0 + 8;
    const int u_glob = bu * 8 + (wn >> 2) + (tq >> 1);
    const int u_ch = u_glob >> 6;       // == bu >> 3
    const int u_c = u_glob & 63;

    // per-thread gx offsets (elements) within a (t,bu) tile of [64][36] f32
    const int gcol = wn + 2 * tq;
    const int gx_o00 = (wm + g) * 36 + gcol;           // mt=0, r0
    const int gx_o01 = (wm + g + 8) * 36 + gcol;       // mt=0, r1
    const int gx_o10 = (wm + 16 + g) * 36 + gcol;      // mt=1, r0
    const int gx_o11 = (wm + 16 + g + 8) * 36 + gcol;  // mt=1, r1

    float creg0 = 0.0f, creg1 = 0.0f;
    float hlast0 = 0.0f, hlast1 = 0.0f;

    for (int t = 0; t < Tt; t++) {
        // gx prefetch into registers (consumed at epilogue; latency hidden)
        const float* gxp = g_gx2 + ((size_t)t * NBLK + bu) * 2304;
        float2 gx00 = __ldg((const float2*)(gxp + gx_o00));
        float2 gx01 = __ldg((const float2*)(gxp + gx_o01));
        float2 gx10 = __ldg((const float2*)(gxp + gx_o10));
        float2 gx11 = __ldg((const float2*)(gxp + gx_o11));

        float C[2][4];
#pragma unroll
        for (int q = 0; q < 4; q++) { C[0][q] = 0.0f; C[1][q] = 0.0f; }

        for (int i = 0; i < 16; i++) {
            if ((i & 3) == 0) MBAR_WAIT(sbase + PMB_OFF + (i >> 2) * 8, t & 1);
            const int ch = (i + chunk0) & 15;

            const uint32_t abuf = sbase + HB_OFF + (uint32_t)ch * HCH_SZ + a_lane_off;
            const uint32_t bco = (uint32_t)ch * 128;  // 64 cols * 2B

            uint32_t fa[2][2][4], fb[2][2];
            ldsm_x2(fb[0], b_base + bco);
            ldsm_x4(fa[0][0], abuf);
            ldsm_x4(fa[0][1], abuf + 2304);
#pragma unroll
            for (int k16 = 0; k16 < 4; k16++) {
                int cur = k16 & 1;
                if (k16 < 3) {
                    int nb = cur ^ 1;
                    uint32_t kb = (uint32_t)(k16 + 1) * 32;
                    ldsm_x2(fb[nb], b_base + bco + kb);
                    ldsm_x4(fa[nb][0], abuf + kb);
                    ldsm_x4(fa[nb][1], abuf + 2304 + kb);
                }
                mma_f16(C[0], fa[cur][0], fb[cur]);
                mma_f16(C[1], fa[cur][1], fb[cur]);
            }
        }

        // ---- epilogue (gx from registers; no wait) ----
        float v[2][4], p[2][4];
        v[0][0] = C[0][0] + gx00.x;
        v[0][1] = C[0][1] + gx00.y;
        v[0][2] = C[0][2] + gx01.x;
        v[0][3] = C[0][3] + gx01.y;
        v[1][0] = C[1][0] + gx10.x;
        v[1][1] = C[1][1] + gx10.y;
        v[1][2] = C[1][2] + gx11.x;
        v[1][3] = C[1][3] + gx11.y;
#pragma unroll
        for (int mt = 0; mt < 2; mt++)
#pragma unroll
            for (int q = 0; q < 4; q++)
                p[mt][q] = __shfl_xor_sync(0xffffffffu, v[mt][q], 1);

        float ii0, ff0, cc0, oo0, ii1, ff1, cc1, oo1;
        if (myMt == 0) {
            ii0 = v[0][0]; ff0 = v[0][1]; cc0 = p[0][0]; oo0 = p[0][1];
            ii1 = v[0][2]; ff1 = v[0][3]; cc1 = p[0][2]; oo1 = p[0][3];
        } else {
            ii0 = p[1][0]; ff0 = p[1][1]; cc0 = v[1][0]; oo0 = v[1][1];
            ii1 = p[1][2]; ff1 = p[1][3]; cc1 = v[1][2]; oo1 = v[1][3];
        }

        float cn0 = fmaf(sigf(ff0), creg0, sigf(ii0) * tanhf_fast(cc0));
        float cn1 = fmaf(sigf(ff1), creg1, sigf(ii1) * tanhf_fast(cc1));
        creg0 = cn0; creg1 = cn1;
        float hn0 = sigf(oo0) * tanhf_fast(cn0);
        float hn1 = sigf(oo1) * tanhf_fast(cn1);
        hlast0 = hn0; hlast1 = hn1;

        const int np = (t + 1) & 1;
        __half* hb = &g_hbulk[np][u_ch][0];
        hb[row0 * 72 + u_c] = __float2half(hn0);
        hb[row1 * 72 + u_c] = __float2half(hn1);

        // early per-warp producer arrival: warp's h stores visible via release
        __syncwarp();
        if (lane == 0) red_release_gpu((int*)&g_ctr16[u_ch * 32], 1);

        // local slot-reuse gate (off the inter-block critical path)
        BAR_COMPUTE();
        if (tid == 0) *sdone = t + 1;

        out[(size_t)t * (Bb * Hh) + row0 * Hh + u_glob] = hn0;
        out[(size_t)t * (Bb * Hh) + row1 * Hh + u_glob] = hn1;
    }

    // final h_T, c_T
    size_t base = (size_t)Tt * Bb * Hh;
    out[base + row0 * Hh + u_glob] = hlast0;
    out[base + row1 * Hh + u_glob] = hlast1;
    out[base + Bb * Hh + row0 * Hh + u_glob] = creg0;
    out[base + Bb * Hh + row1 * Hh + u_glob] = creg1;
}

// ---------------------------------------------------------------------------
extern "C" void kernel_launch(void* const* d_in, const int* in_sizes, int n_in,
                              void* d_out, int out_size) {
    const float* x  = (const float*)d_in[0];
    const float* Wi = (const float*)d_in[1];
    const float* bi = (const float*)d_in[2];
    const float* Wf = (const float*)d_in[3];
    const float* bf = (const float*)d_in[4];
    const float* Wc = (const float*)d_in[5];
    const float* bc = (const float*)d_in[6];
    const float* Wo = (const float*)d_in[7];
    const float* bo = (const float*)d_in[8];
    float* out = (float*)d_out;

    cudaFuncSetAttribute(gemm_x_mma, cudaFuncAttributeMaxDynamicSharedMemorySize, GX_SMEM);
    cudaFuncSetAttribute(lstm_persist, cudaFuncAttributeMaxDynamicSharedMemorySize, PERSIST_SMEM);

    repack_kernel<<<512, 256>>>(Wi, Wf, Wc, Wo, bi, bf, bc, bo);
    split_x_kernel<<<1024, 256>>>(x);
    init_state_kernel<<<512, 256>>>();

    gemm_x_mma<<<dim3(G4 / 128, (Tt * Bb) / 128), 256, GX_SMEM>>>();

    lstm_persist<<<NBLK, 288, PERSIST_SMEM>>>(out);
}